// round 12
// baseline (speedup 1.0000x reference)
#include <cuda_runtime.h>
#include <cuda_bf16.h>
#include <cstdint>

// ---------------------------------------------------------------------------
// out = x @ (W + ALPHA*E)^T + b  folded into ONE GEMM on the HMMA path
// (tcgen05 unavailable: harness compiles PTX at .target sm_103 — no 'a').
// fp32 emulated via bf16 split-2:  x = Ah+Al,  Wt = Bh+Bl
//   x*Wt ~= Ah*Bh + Al*Bh + Ah*Bl   (3 virtual K-segments, K'=3072)
// R11: persistent GEMM (2 CTA/SM, tile loop, cross-tile cp.async overlap),
//      no redundant trailing barrier, last-chunk wait fixed to 0,
//      build_tt fused into convert_x (blocks 0/1), one fewer launch.
// ---------------------------------------------------------------------------

#define D_DIM 1024
#define M_ROWS 16384
#define ALPHA_F 16.0f
#define NTILES ((M_ROWS / 128) * (D_DIM / 128))   // 1024

__device__ float g_A3[D_DIM * 8];   // [d][p3]
__device__ float g_C1[D_DIM * 8];   // [o][p3] (pre-scaled by ALPHA)
__device__ __align__(16) __nv_bfloat16 g_A[(size_t)M_ROWS * 2048];  // [row][Ah|Al]
__device__ __align__(16) __nv_bfloat16 g_B2[(size_t)D_DIM * 2048];  // [o][Bh|Bl]

// ---------------------------------------------------------------------------
__device__ __forceinline__ uint32_t smem_u32(const void* p) {
    uint32_t a;
    asm("{ .reg .u64 t; cvta.to.shared.u64 t, %1; cvt.u32.u64 %0, t; }" : "=r"(a) : "l"(p));
    return a;
}
#define CP_ASYNC16(dst, src) \
    asm volatile("cp.async.cg.shared.global [%0], [%1], 16;" :: "r"(dst), "l"(src))
#define CP_COMMIT() asm volatile("cp.async.commit_group;" ::: "memory")
#define CP_WAIT(n)  asm volatile("cp.async.wait_group %0;" :: "n"(n) : "memory")

#define LDSM_X4(r0, r1, r2, r3, a) \
    asm volatile("ldmatrix.sync.aligned.m8n8.x4.shared.b16 {%0,%1,%2,%3}, [%4];" \
                 : "=r"(r0), "=r"(r1), "=r"(r2), "=r"(r3) : "r"(a))

#define MMA16816(d, a, b0, b1) \
    asm volatile("mma.sync.aligned.m16n8k16.row.col.f32.bf16.bf16.f32 " \
                 "{%0,%1,%2,%3}, {%4,%5,%6,%7}, {%8,%9}, {%0,%1,%2,%3};" \
                 : "+f"((d)[0]), "+f"((d)[1]), "+f"((d)[2]), "+f"((d)[3]) \
                 : "r"((a)[0]), "r"((a)[1]), "r"((a)[2]), "r"((a)[3]), \
                   "r"(b0), "r"(b1))

// ---------------------------------------------------------------------------
// Kernel 1: x -> [Ah | Al] bf16 split.  Blocks 0/1 additionally compute the
// TT core chains (m-side -> g_A3, n-side -> g_C1), hidden under the DRAM wall.
// ---------------------------------------------------------------------------
__global__ void convert_x(const float* __restrict__ x,
                          const float* __restrict__ c0, const float* __restrict__ c1,
                          const float* __restrict__ c2, const float* __restrict__ c3,
                          const float* __restrict__ c4, const float* __restrict__ c5) {
    __shared__ float sA[1024], sB[512], tmp[1024], first[64];

    size_t i = (size_t)blockIdx.x * 256 + threadIdx.x;   // float4 index
    float4 v = ((const float4*)x)[i];
    size_t r = i >> 8;
    int c = (int)(i & 255) * 4;
    __nv_bfloat16 h[4], l[4];
    float f[4] = {v.x, v.y, v.z, v.w};
    #pragma unroll
    for (int j = 0; j < 4; j++) {
        h[j] = __float2bfloat16_rn(f[j]);
        l[j] = __float2bfloat16_rn(f[j] - __bfloat162float(h[j]));
    }
    *(uint2*)&g_A[r * 2048 + c]        = *(uint2*)h;
    *(uint2*)&g_A[r * 2048 + 1024 + c] = *(uint2*)l;

    // ---- TT chains on blocks 0/1 only ----
    if (blockIdx.x >= 2) return;
    int t = threadIdx.x;
    if (blockIdx.x == 0) {
        for (int k = t; k < 1024; k += 256) sA[k] = c1[k];
        for (int k = t; k < 512;  k += 256) sB[k] = c2[k];
        if (t < 64) first[t] = c0[t];
        __syncthreads();
        for (int k = t; k < 1024; k += 256) {
            int row = k >> 3, p2 = k & 7, m2 = row >> 3, m1 = row & 7;
            float s = 0.f;
            #pragma unroll
            for (int p1 = 0; p1 < 8; p1++) s += first[m1 * 8 + p1] * sA[p1 * 128 + m2 * 8 + p2];
            tmp[k] = s;
        }
        __syncthreads();
        for (int k = t; k < 8192; k += 256) {
            int d = k >> 3, p3 = k & 7, m3 = d >> 7, rem = d & 127;
            float s = 0.f;
            #pragma unroll
            for (int p2 = 0; p2 < 8; p2++) s += tmp[rem * 8 + p2] * sB[p2 * 64 + m3 * 8 + p3];
            g_A3[k] = s;
        }
    } else {
        for (int k = t; k < 1024; k += 256) sA[k] = c4[k];
        for (int k = t; k < 512;  k += 256) sB[k] = c3[k];
        if (t < 64) { int n3 = t >> 3, p5 = t & 7; first[n3 * 8 + p5] = c5[p5 * 8 + n3]; }
        __syncthreads();
        for (int k = t; k < 1024; k += 256) {
            int row = k >> 3, p4 = k & 7, n2 = row >> 3, n3 = row & 7;
            float s = 0.f;
            #pragma unroll
            for (int p5 = 0; p5 < 8; p5++) s += sA[p4 * 128 + n2 * 8 + p5] * first[n3 * 8 + p5];
            tmp[k] = s;
        }
        __syncthreads();
        for (int k = t; k < 8192; k += 256) {
            int o = k >> 3, p3 = k & 7, n1 = o >> 7, rem = o & 127;
            float s = 0.f;
            #pragma unroll
            for (int p4 = 0; p4 < 8; p4++) s += sB[p3 * 64 + n1 * 8 + p4] * tmp[rem * 8 + p4];
            g_C1[k] = ALPHA_F * s;
        }
    }
}

// ---------------------------------------------------------------------------
// Kernel 2: Wt = W + A3*C1^T, split -> g_B2 = [Bh | Bl]
// ---------------------------------------------------------------------------
__global__ void combine_w(const float* __restrict__ W) {
    int o = blockIdx.x;
    __shared__ float cl[8];
    if (threadIdx.x < 8) cl[threadIdx.x] = g_C1[o * 8 + threadIdx.x];
    __syncthreads();
    float c0 = cl[0], c1 = cl[1], c2 = cl[2], c3 = cl[3];
    float c4 = cl[4], c5 = cl[5], c6 = cl[6], c7 = cl[7];
    for (int d = threadIdx.x; d < D_DIM; d += 256) {
        const float4* a = (const float4*)&g_A3[d * 8];
        float4 a0 = a[0], a1 = a[1];
        float s = W[(size_t)o * D_DIM + d];
        s += a0.x * c0 + a0.y * c1 + a0.z * c2 + a0.w * c3;
        s += a1.x * c4 + a1.y * c5 + a1.z * c6 + a1.w * c7;
        __nv_bfloat16 hb = __float2bfloat16_rn(s);
        __nv_bfloat16 lb = __float2bfloat16_rn(s - __bfloat162float(hb));
        g_B2[(size_t)o * 2048 + d]        = hb;
        g_B2[(size_t)o * 2048 + 1024 + d] = lb;
    }
}

// ---------------------------------------------------------------------------
// Kernel 3: persistent HMMA GEMM. CTA 128x128, BK=64, 3-stage cp.async,
// 2 CTA/SM, each CTA loops over tiles (t += gridDim.x).
// 8 warps: warp (wm=w>>2, wn=w&3) owns 64(m) x 32(n).
// Virtual K: 48 chunks = [Ah*Bh]x16 + [Al*Bh]x16 + [Ah*Bl]x16.
// XOR swizzle: col16B ^= (row&7)<<4.  No trailing barrier (top barrier at
// iter c+1 orders iter-c reads before the stage-(c%3) rewrite).
// ---------------------------------------------------------------------------
#define NSTAGE 3
#define STAGE_BYTES 32768
#define SMEM_TOTAL (NSTAGE * STAGE_BYTES)
#define NCHUNK 48

extern __shared__ __align__(1024) char smem[];

__global__ __launch_bounds__(256, 2) void gemm_mma(const float* __restrict__ bias,
                                                   float* __restrict__ out) {
    const int tid = threadIdx.x;
    const uint32_t sbase = smem_u32(smem);
    const int w = tid >> 5, l = tid & 31;
    const int wm = w >> 2, wn = w & 3;

    // tile-invariant pieces of the cp.async mapping
    uint32_t cp_dst[4];
    int cp_row[4], cp_seg[4];
    #pragma unroll
    for (int i = 0; i < 4; i++) {
        int v = tid + 256 * i;            // 0..1023
        int row = v >> 3, seg = v & 7;
        cp_row[i] = row; cp_seg[i] = seg;
        cp_dst[i] = (uint32_t)(row * 128 + ((seg * 16) ^ ((row & 7) << 4)));
    }

    // ldmatrix lane address components (tile-invariant)
    const int arow = wm * 64 + (l & 15);
    const uint32_t axr = (uint32_t)((arow & 7) << 4);
    const uint32_t arb = (uint32_t)(arow * 128);
    const uint32_t ah16 = (uint32_t)((l >> 4) * 16);
    const int brow = wn * 32 + ((l >> 4) * 8) + (l & 7);
    const uint32_t bxr = (uint32_t)((l & 7) << 4);
    const uint32_t brb = (uint32_t)(brow * 128);
    const uint32_t bh16 = (uint32_t)(((l >> 3) & 1) * 16);

    for (int tt = blockIdx.x; tt < NTILES; tt += gridDim.x) {
        const int bn = (tt & 7) * 128;
        const int bm = (tt >> 3) * 128;

        const __nv_bfloat16* srcA[4];
        const __nv_bfloat16* srcB[4];
        #pragma unroll
        for (int i = 0; i < 4; i++) {
            srcA[i] = g_A  + (size_t)(bm + cp_row[i]) * 2048 + cp_seg[i] * 8;
            srcB[i] = g_B2 + (size_t)(bn + cp_row[i]) * 2048 + cp_seg[i] * 8;
        }

        float acc[4][4][4];
        #pragma unroll
        for (int i = 0; i < 4; i++)
            #pragma unroll
            for (int j = 0; j < 4; j++)
                #pragma unroll
                for (int k = 0; k < 4; k++) acc[i][j][k] = 0.f;

        // segment offsets per chunk: A [Ah|Al|Ah], B [Bh|Bh|Bl]
        auto issue_stage = [&](int s) {
            int seg = s >> 4, kk = (s & 15) * 64;
            int aoff = (seg == 1) ? 1024 + kk : kk;
            int boff = (seg == 2) ? 1024 + kk : kk;
            uint32_t dA = sbase + (s % NSTAGE) * STAGE_BYTES;
            uint32_t dB = dA + 16384;
            #pragma unroll
            for (int i = 0; i < 4; i++) CP_ASYNC16(dA + cp_dst[i], srcA[i] + aoff);
            #pragma unroll
            for (int i = 0; i < 4; i++) CP_ASYNC16(dB + cp_dst[i], srcB[i] + boff);
            CP_COMMIT();
        };

        issue_stage(0); issue_stage(1);

        for (int c = 0; c < NCHUNK; c++) {
            if (c == NCHUNK - 1) CP_WAIT(0); else CP_WAIT(1);
            __syncthreads();
            if (c + 2 < NCHUNK) issue_stage(c + 2);

            const uint32_t sA = sbase + (c % NSTAGE) * STAGE_BYTES;
            const uint32_t sB = sA + 16384;
            #pragma unroll
            for (int ks = 0; ks < 4; ks++) {
                uint32_t a[4][4];
                uint32_t br[2][4];
                const uint32_t ac = (uint32_t)(ks * 32) + ah16;
                const uint32_t bc = (uint32_t)(ks * 32) + bh16;
                #pragma unroll
                for (int mf = 0; mf < 4; mf++)
                    LDSM_X4(a[mf][0], a[mf][1], a[mf][2], a[mf][3],
                            sA + arb + mf * 2048 + (ac ^ axr));
                #pragma unroll
                for (int nf2 = 0; nf2 < 2; nf2++)
                    LDSM_X4(br[nf2][0], br[nf2][1], br[nf2][2], br[nf2][3],
                            sB + brb + nf2 * 2048 + (bc ^ bxr));
                #pragma unroll
                for (int mf = 0; mf < 4; mf++)
                    #pragma unroll
                    for (int nf = 0; nf < 4; nf++)
                        MMA16816(acc[mf][nf], a[mf],
                                 br[nf >> 1][(nf & 1) * 2], br[nf >> 1][(nf & 1) * 2 + 1]);
            }
            // no trailing barrier: next iter's top barrier orders the
            // stage-(c%3) rewrite (issued at iter c+1) after this iter's reads
        }

        // ---- epilogue: bias + store (regs + gmem only; no smem hazard with
        //      the next tile's prologue issues, which target stages 0/1) ----
        float2 bv[4];
        #pragma unroll
        for (int nf = 0; nf < 4; nf++) {
            int col = bn + wn * 32 + nf * 8 + (l & 3) * 2;
            bv[nf] = *(const float2*)(bias + col);
        }
        #pragma unroll
        for (int mf = 0; mf < 4; mf++) {
            int r0 = bm + wm * 64 + mf * 16 + (l >> 2);
            #pragma unroll
            for (int nf = 0; nf < 4; nf++) {
                int col = bn + wn * 32 + nf * 8 + (l & 3) * 2;
                float2 v0 = {acc[mf][nf][0] + bv[nf].x, acc[mf][nf][1] + bv[nf].y};
                float2 v1 = {acc[mf][nf][2] + bv[nf].x, acc[mf][nf][3] + bv[nf].y};
                *(float2*)(out + (size_t)r0 * D_DIM + col) = v0;
                *(float2*)(out + (size_t)(r0 + 8) * D_DIM + col) = v1;
            }
        }
    }
}

// ---------------------------------------------------------------------------
extern "C" void kernel_launch(void* const* d_in, const int* in_sizes, int n_in,
                              void* d_out, int out_size) {
    const float* x  = (const float*)d_in[0];
    const float* W  = (const float*)d_in[1];
    const float* b  = (const float*)d_in[2];
    const float* c0 = (const float*)d_in[3];
    const float* c1 = (const float*)d_in[4];
    const float* c2 = (const float*)d_in[5];
    const float* c3 = (const float*)d_in[6];
    const float* c4 = (const float*)d_in[7];
    const float* c5 = (const float*)d_in[8];
    float* out = (float*)d_out;

    cudaFuncSetAttribute(gemm_mma, cudaFuncAttributeMaxDynamicSharedMemorySize, SMEM_TOTAL);

    convert_x<<<(M_ROWS * D_DIM / 4) / 256, 256>>>(x, c0, c1, c2, c3, c4, c5);
    combine_w<<<D_DIM, 256>>>(W);

    int sm_count = 0;
    cudaDeviceGetAttribute(&sm_count, cudaDevAttrMultiProcessorCount, 0);
    if (sm_count <= 0) sm_count = 148;
    gemm_mma<<<2 * sm_count, 256, SMEM_TOTAL>>>(b, out);
}

// round 13
// speedup vs baseline: 1.5980x; 1.5980x over previous
#include <cuda_runtime.h>
#include <cuda_bf16.h>
#include <cstdint>

// ---------------------------------------------------------------------------
// out = x @ (W + ALPHA*E)^T + b  folded into ONE GEMM on the HMMA path
// (tcgen05 unavailable: harness compiles PTX at .target sm_103 — no 'a').
// fp32 emulated via bf16 split-2:  x = Ah+Al,  Wt = Bh+Bl
//   x*Wt ~= Ah*Bh + Al*Bh + Ah*Bl   (3 virtual K-segments, K'=3072)
// R13: revert persistent loop (caused reg spills past the 128-reg cap);
//      static 1024-CTA grid as in the 278.9us best, PLUS:
//      - trailing per-chunk __syncthreads removed (top barrier suffices)
//      - last-chunk CP_WAIT(0) fix
//      - build_tt stays fused into convert_x
// ---------------------------------------------------------------------------

#define D_DIM 1024
#define M_ROWS 16384
#define ALPHA_F 16.0f

__device__ float g_A3[D_DIM * 8];   // [d][p3]
__device__ float g_C1[D_DIM * 8];   // [o][p3] (pre-scaled by ALPHA)
__device__ __align__(16) __nv_bfloat16 g_A[(size_t)M_ROWS * 2048];  // [row][Ah|Al]
__device__ __align__(16) __nv_bfloat16 g_B2[(size_t)D_DIM * 2048];  // [o][Bh|Bl]

// ---------------------------------------------------------------------------
__device__ __forceinline__ uint32_t smem_u32(const void* p) {
    uint32_t a;
    asm("{ .reg .u64 t; cvta.to.shared.u64 t, %1; cvt.u32.u64 %0, t; }" : "=r"(a) : "l"(p));
    return a;
}
#define CP_ASYNC16(dst, src) \
    asm volatile("cp.async.cg.shared.global [%0], [%1], 16;" :: "r"(dst), "l"(src))
#define CP_COMMIT() asm volatile("cp.async.commit_group;" ::: "memory")
#define CP_WAIT(n)  asm volatile("cp.async.wait_group %0;" :: "n"(n) : "memory")

#define LDSM_X4(r0, r1, r2, r3, a) \
    asm volatile("ldmatrix.sync.aligned.m8n8.x4.shared.b16 {%0,%1,%2,%3}, [%4];" \
                 : "=r"(r0), "=r"(r1), "=r"(r2), "=r"(r3) : "r"(a))

#define MMA16816(d, a, b0, b1) \
    asm volatile("mma.sync.aligned.m16n8k16.row.col.f32.bf16.bf16.f32 " \
                 "{%0,%1,%2,%3}, {%4,%5,%6,%7}, {%8,%9}, {%0,%1,%2,%3};" \
                 : "+f"((d)[0]), "+f"((d)[1]), "+f"((d)[2]), "+f"((d)[3]) \
                 : "r"((a)[0]), "r"((a)[1]), "r"((a)[2]), "r"((a)[3]), \
                   "r"(b0), "r"(b1))

// ---------------------------------------------------------------------------
// Kernel 1: x -> [Ah | Al] bf16 split.  Blocks 0/1 additionally compute the
// TT core chains (m-side -> g_A3, n-side -> g_C1), hidden under the DRAM wall.
// ---------------------------------------------------------------------------
__global__ void convert_x(const float* __restrict__ x,
                          const float* __restrict__ c0, const float* __restrict__ c1,
                          const float* __restrict__ c2, const float* __restrict__ c3,
                          const float* __restrict__ c4, const float* __restrict__ c5) {
    __shared__ float sA[1024], sB[512], tmp[1024], first[64];

    size_t i = (size_t)blockIdx.x * 256 + threadIdx.x;   // float4 index
    float4 v = ((const float4*)x)[i];
    size_t r = i >> 8;
    int c = (int)(i & 255) * 4;
    __nv_bfloat16 h[4], l[4];
    float f[4] = {v.x, v.y, v.z, v.w};
    #pragma unroll
    for (int j = 0; j < 4; j++) {
        h[j] = __float2bfloat16_rn(f[j]);
        l[j] = __float2bfloat16_rn(f[j] - __bfloat162float(h[j]));
    }
    *(uint2*)&g_A[r * 2048 + c]        = *(uint2*)h;
    *(uint2*)&g_A[r * 2048 + 1024 + c] = *(uint2*)l;

    // ---- TT chains on blocks 0/1 only ----
    if (blockIdx.x >= 2) return;
    int t = threadIdx.x;
    if (blockIdx.x == 0) {
        for (int k = t; k < 1024; k += 256) sA[k] = c1[k];
        for (int k = t; k < 512;  k += 256) sB[k] = c2[k];
        if (t < 64) first[t] = c0[t];
        __syncthreads();
        for (int k = t; k < 1024; k += 256) {
            int row = k >> 3, p2 = k & 7, m2 = row >> 3, m1 = row & 7;
            float s = 0.f;
            #pragma unroll
            for (int p1 = 0; p1 < 8; p1++) s += first[m1 * 8 + p1] * sA[p1 * 128 + m2 * 8 + p2];
            tmp[k] = s;
        }
        __syncthreads();
        for (int k = t; k < 8192; k += 256) {
            int d = k >> 3, p3 = k & 7, m3 = d >> 7, rem = d & 127;
            float s = 0.f;
            #pragma unroll
            for (int p2 = 0; p2 < 8; p2++) s += tmp[rem * 8 + p2] * sB[p2 * 64 + m3 * 8 + p3];
            g_A3[k] = s;
        }
    } else {
        for (int k = t; k < 1024; k += 256) sA[k] = c4[k];
        for (int k = t; k < 512;  k += 256) sB[k] = c3[k];
        if (t < 64) { int n3 = t >> 3, p5 = t & 7; first[n3 * 8 + p5] = c5[p5 * 8 + n3]; }
        __syncthreads();
        for (int k = t; k < 1024; k += 256) {
            int row = k >> 3, p4 = k & 7, n2 = row >> 3, n3 = row & 7;
            float s = 0.f;
            #pragma unroll
            for (int p5 = 0; p5 < 8; p5++) s += sA[p4 * 128 + n2 * 8 + p5] * first[n3 * 8 + p5];
            tmp[k] = s;
        }
        __syncthreads();
        for (int k = t; k < 8192; k += 256) {
            int o = k >> 3, p3 = k & 7, n1 = o >> 7, rem = o & 127;
            float s = 0.f;
            #pragma unroll
            for (int p4 = 0; p4 < 8; p4++) s += sB[p3 * 64 + n1 * 8 + p4] * tmp[rem * 8 + p4];
            g_C1[k] = ALPHA_F * s;
        }
    }
}

// ---------------------------------------------------------------------------
// Kernel 2: Wt = W + A3*C1^T, split -> g_B2 = [Bh | Bl]
// ---------------------------------------------------------------------------
__global__ void combine_w(const float* __restrict__ W) {
    int o = blockIdx.x;
    __shared__ float cl[8];
    if (threadIdx.x < 8) cl[threadIdx.x] = g_C1[o * 8 + threadIdx.x];
    __syncthreads();
    float c0 = cl[0], c1 = cl[1], c2 = cl[2], c3 = cl[3];
    float c4 = cl[4], c5 = cl[5], c6 = cl[6], c7 = cl[7];
    for (int d = threadIdx.x; d < D_DIM; d += 256) {
        const float4* a = (const float4*)&g_A3[d * 8];
        float4 a0 = a[0], a1 = a[1];
        float s = W[(size_t)o * D_DIM + d];
        s += a0.x * c0 + a0.y * c1 + a0.z * c2 + a0.w * c3;
        s += a1.x * c4 + a1.y * c5 + a1.z * c6 + a1.w * c7;
        __nv_bfloat16 hb = __float2bfloat16_rn(s);
        __nv_bfloat16 lb = __float2bfloat16_rn(s - __bfloat162float(hb));
        g_B2[(size_t)o * 2048 + d]        = hb;
        g_B2[(size_t)o * 2048 + 1024 + d] = lb;
    }
}

// ---------------------------------------------------------------------------
// Kernel 3: HMMA GEMM. CTA 128x128, BK=64 bf16, 3-stage cp.async, 2 CTA/SM,
// static grid (one tile per CTA — persistent variant spilled regs, reverted).
// 8 warps: warp (wm=w>>2, wn=w&3) owns 64(m) x 32(n).
// Virtual K: 48 chunks = [Ah*Bh]x16 + [Al*Bh]x16 + [Ah*Bl]x16.
// XOR swizzle: col16B ^= (row&7)<<4.
// No trailing per-chunk barrier: the top barrier at iter c+1 orders iter-c
// smem reads before the stage-(c%3) rewrite issued at iter c+1.
// ---------------------------------------------------------------------------
#define NSTAGE 3
#define STAGE_BYTES 32768
#define SMEM_TOTAL (NSTAGE * STAGE_BYTES)
#define NCHUNK 48

extern __shared__ __align__(1024) char smem[];

__global__ __launch_bounds__(256, 2) void gemm_mma(const float* __restrict__ bias,
                                                   float* __restrict__ out) {
    const int tid = threadIdx.x;
    const int bn = blockIdx.x * 128;
    const int bm = blockIdx.y * 128;
    const uint32_t sbase = smem_u32(smem);

    const int w = tid >> 5, l = tid & 31;
    const int wm = w >> 2, wn = w & 3;

    // ---- cp.async lane mapping: 8 vectors (4 A + 4 B) of 16B per thread ----
    uint32_t cp_dst[4];
    const __nv_bfloat16* cp_srcA[4];
    const __nv_bfloat16* cp_srcB[4];
    #pragma unroll
    for (int i = 0; i < 4; i++) {
        int v = tid + 256 * i;            // 0..1023
        int row = v >> 3, seg = v & 7;
        cp_dst[i]  = (uint32_t)(row * 128 + ((seg * 16) ^ ((row & 7) << 4)));
        cp_srcA[i] = g_A  + (size_t)(bm + row) * 2048 + seg * 8;
        cp_srcB[i] = g_B2 + (size_t)(bn + row) * 2048 + seg * 8;
    }

    // ---- ldmatrix lane address components ----
    const int arow = wm * 64 + (l & 15);
    const uint32_t axr = (uint32_t)((arow & 7) << 4);
    const uint32_t arb = (uint32_t)(arow * 128);
    const uint32_t ah16 = (uint32_t)((l >> 4) * 16);
    const int brow = wn * 32 + ((l >> 4) * 8) + (l & 7);
    const uint32_t bxr = (uint32_t)((l & 7) << 4);
    const uint32_t brb = (uint32_t)(brow * 128);
    const uint32_t bh16 = (uint32_t)(((l >> 3) & 1) * 16);

    float acc[4][4][4];
    #pragma unroll
    for (int i = 0; i < 4; i++)
        #pragma unroll
        for (int j = 0; j < 4; j++)
            #pragma unroll
            for (int k = 0; k < 4; k++) acc[i][j][k] = 0.f;

    // segment offsets (elements) per chunk: A [Ah|Al|Ah], B [Bh|Bh|Bl]
    auto issue_stage = [&](int t) {
        int seg = t >> 4, kk = (t & 15) * 64;
        int aoff = (seg == 1) ? 1024 + kk : kk;
        int boff = (seg == 2) ? 1024 + kk : kk;
        uint32_t sA = sbase + (t % NSTAGE) * STAGE_BYTES;
        uint32_t sB = sA + 16384;
        #pragma unroll
        for (int i = 0; i < 4; i++) CP_ASYNC16(sA + cp_dst[i], cp_srcA[i] + aoff);
        #pragma unroll
        for (int i = 0; i < 4; i++) CP_ASYNC16(sB + cp_dst[i], cp_srcB[i] + boff);
        CP_COMMIT();
    };

    issue_stage(0); issue_stage(1);

    for (int c = 0; c < NCHUNK; c++) {
        // At iter c the newest outstanding cp.async group is stage c+1, so
        // wait_group 1 guarantees stage c -- EXCEPT at the last chunk, where
        // stage c is itself the newest group (nothing issued beyond it).
        if (c == NCHUNK - 1) CP_WAIT(0); else CP_WAIT(1);
        __syncthreads();
        if (c + 2 < NCHUNK) issue_stage(c + 2);

        const uint32_t sA = sbase + (c % NSTAGE) * STAGE_BYTES;
        const uint32_t sB = sA + 16384;
        #pragma unroll
        for (int ks = 0; ks < 4; ks++) {
            uint32_t a[4][4];
            uint32_t br[2][4];
            const uint32_t ac = (uint32_t)(ks * 32) + ah16;
            const uint32_t bc = (uint32_t)(ks * 32) + bh16;
            #pragma unroll
            for (int mf = 0; mf < 4; mf++)
                LDSM_X4(a[mf][0], a[mf][1], a[mf][2], a[mf][3],
                        sA + arb + mf * 2048 + (ac ^ axr));
            #pragma unroll
            for (int nf2 = 0; nf2 < 2; nf2++)
                LDSM_X4(br[nf2][0], br[nf2][1], br[nf2][2], br[nf2][3],
                        sB + brb + nf2 * 2048 + (bc ^ bxr));
            #pragma unroll
            for (int mf = 0; mf < 4; mf++)
                #pragma unroll
                for (int nf = 0; nf < 4; nf++)
                    MMA16816(acc[mf][nf], a[mf],
                             br[nf >> 1][(nf & 1) * 2], br[nf >> 1][(nf & 1) * 2 + 1]);
        }
        // no trailing barrier: next iter's top barrier orders the
        // stage-(c%3) rewrite (issued at iter c+1) after this iter's reads
    }

    // ---- epilogue: bias + store ----
    float2 bv[4];
    #pragma unroll
    for (int nf = 0; nf < 4; nf++) {
        int col = bn + wn * 32 + nf * 8 + (l & 3) * 2;
        bv[nf] = *(const float2*)(bias + col);
    }
    #pragma unroll
    for (int mf = 0; mf < 4; mf++) {
        int r0 = bm + wm * 64 + mf * 16 + (l >> 2);
        #pragma unroll
        for (int nf = 0; nf < 4; nf++) {
            int col = bn + wn * 32 + nf * 8 + (l & 3) * 2;
            float2 v0 = {acc[mf][nf][0] + bv[nf].x, acc[mf][nf][1] + bv[nf].y};
            float2 v1 = {acc[mf][nf][2] + bv[nf].x, acc[mf][nf][3] + bv[nf].y};
            *(float2*)(out + (size_t)r0 * D_DIM + col) = v0;
            *(float2*)(out + (size_t)(r0 + 8) * D_DIM + col) = v1;
        }
    }
}

// ---------------------------------------------------------------------------
extern "C" void kernel_launch(void* const* d_in, const int* in_sizes, int n_in,
                              void* d_out, int out_size) {
    const float* x  = (const float*)d_in[0];
    const float* W  = (const float*)d_in[1];
    const float* b  = (const float*)d_in[2];
    const float* c0 = (const float*)d_in[3];
    const float* c1 = (const float*)d_in[4];
    const float* c2 = (const float*)d_in[5];
    const float* c3 = (const float*)d_in[6];
    const float* c4 = (const float*)d_in[7];
    const float* c5 = (const float*)d_in[8];
    float* out = (float*)d_out;

    cudaFuncSetAttribute(gemm_mma, cudaFuncAttributeMaxDynamicSharedMemorySize, SMEM_TOTAL);

    convert_x<<<(M_ROWS * D_DIM / 4) / 256, 256>>>(x, c0, c1, c2, c3, c4, c5);
    combine_w<<<D_DIM, 256>>>(W);
    dim3 grid(D_DIM / 128, M_ROWS / 128);
    gemm_mma<<<grid, 256, SMEM_TOTAL>>>(b, out);
}

// round 14
// speedup vs baseline: 2.3683x; 1.4820x over previous
#include <cuda_runtime.h>
#include <cuda_fp16.h>
#include <cstdint>

// ---------------------------------------------------------------------------
// out = x @ (W + ALPHA*E)^T + b  folded into ONE GEMM on the HMMA path.
// R14 precision scheme (fp16 split on the WEIGHT side only):
//   Wt = Wh + Wl (fp16 pair, exact to ~2^-22),  xh = fp16(x)
//   out ~= xh*Wh + xh*Wl          (dropped term xl*Wt ~ 2^-11/sqrt(3) rel)
// Virtual K = 2048 (33% less MMA work than the bf16 3-segment scheme), and
// each A tile is loaded once per chunk and multiplied by BOTH B tiles.
// GEMM: CTA 128x128, BK=64, stage={A,Bh,Bl}=48KB, 2 stages, 2 CTA/SM,
// 16 chunks, fp32 accum.
// ---------------------------------------------------------------------------

#define D_DIM 1024
#define M_ROWS 16384
#define ALPHA_F 16.0f

__device__ float g_A3[D_DIM * 8];   // [d][p3]
__device__ float g_C1[D_DIM * 8];   // [o][p3] (pre-scaled by ALPHA)
__device__ __align__(16) __half g_A[(size_t)M_ROWS * 1024];   // xh
__device__ __align__(16) __half g_B2[(size_t)D_DIM * 2048];   // [o][Wh|Wl]

// ---------------------------------------------------------------------------
__device__ __forceinline__ uint32_t smem_u32(const void* p) {
    uint32_t a;
    asm("{ .reg .u64 t; cvta.to.shared.u64 t, %1; cvt.u32.u64 %0, t; }" : "=r"(a) : "l"(p));
    return a;
}
#define CP_ASYNC16(dst, src) \
    asm volatile("cp.async.cg.shared.global [%0], [%1], 16;" :: "r"(dst), "l"(src))
#define CP_COMMIT() asm volatile("cp.async.commit_group;" ::: "memory")
#define CP_WAIT0()  asm volatile("cp.async.wait_group 0;" ::: "memory")

#define LDSM_X4(r0, r1, r2, r3, a) \
    asm volatile("ldmatrix.sync.aligned.m8n8.x4.shared.b16 {%0,%1,%2,%3}, [%4];" \
                 : "=r"(r0), "=r"(r1), "=r"(r2), "=r"(r3) : "r"(a))

#define MMA16816(d, a, b0, b1) \
    asm volatile("mma.sync.aligned.m16n8k16.row.col.f32.f16.f16.f32 " \
                 "{%0,%1,%2,%3}, {%4,%5,%6,%7}, {%8,%9}, {%0,%1,%2,%3};" \
                 : "+f"((d)[0]), "+f"((d)[1]), "+f"((d)[2]), "+f"((d)[3]) \
                 : "r"((a)[0]), "r"((a)[1]), "r"((a)[2]), "r"((a)[3]), \
                   "r"(b0), "r"(b1))

// ---------------------------------------------------------------------------
// Kernel 1: x -> xh (fp16). 8 floats per thread (16B fp16 store).
// Blocks 0/1 additionally compute the TT core chains, hidden under DRAM.
// ---------------------------------------------------------------------------
__global__ void convert_x(const float* __restrict__ x,
                          const float* __restrict__ c0, const float* __restrict__ c1,
                          const float* __restrict__ c2, const float* __restrict__ c3,
                          const float* __restrict__ c4, const float* __restrict__ c5) {
    __shared__ float sA[1024], sB[512], tmp[1024], first[64];

    size_t i = (size_t)blockIdx.x * 256 + threadIdx.x;   // 8-float unit index
    float4 v0 = ((const float4*)x)[i * 2];
    float4 v1 = ((const float4*)x)[i * 2 + 1];
    __half h[8];
    h[0] = __float2half_rn(v0.x); h[1] = __float2half_rn(v0.y);
    h[2] = __float2half_rn(v0.z); h[3] = __float2half_rn(v0.w);
    h[4] = __float2half_rn(v1.x); h[5] = __float2half_rn(v1.y);
    h[6] = __float2half_rn(v1.z); h[7] = __float2half_rn(v1.w);
    *(uint4*)&g_A[i * 8] = *(uint4*)h;

    // ---- TT chains on blocks 0/1 only ----
    if (blockIdx.x >= 2) return;
    int t = threadIdx.x;
    if (blockIdx.x == 0) {
        for (int k = t; k < 1024; k += 256) sA[k] = c1[k];
        for (int k = t; k < 512;  k += 256) sB[k] = c2[k];
        if (t < 64) first[t] = c0[t];
        __syncthreads();
        for (int k = t; k < 1024; k += 256) {
            int row = k >> 3, p2 = k & 7, m2 = row >> 3, m1 = row & 7;
            float s = 0.f;
            #pragma unroll
            for (int p1 = 0; p1 < 8; p1++) s += first[m1 * 8 + p1] * sA[p1 * 128 + m2 * 8 + p2];
            tmp[k] = s;
        }
        __syncthreads();
        for (int k = t; k < 8192; k += 256) {
            int d = k >> 3, p3 = k & 7, m3 = d >> 7, rem = d & 127;
            float s = 0.f;
            #pragma unroll
            for (int p2 = 0; p2 < 8; p2++) s += tmp[rem * 8 + p2] * sB[p2 * 64 + m3 * 8 + p3];
            g_A3[k] = s;
        }
    } else {
        for (int k = t; k < 1024; k += 256) sA[k] = c4[k];
        for (int k = t; k < 512;  k += 256) sB[k] = c3[k];
        if (t < 64) { int n3 = t >> 3, p5 = t & 7; first[n3 * 8 + p5] = c5[p5 * 8 + n3]; }
        __syncthreads();
        for (int k = t; k < 1024; k += 256) {
            int row = k >> 3, p4 = k & 7, n2 = row >> 3, n3 = row & 7;
            float s = 0.f;
            #pragma unroll
            for (int p5 = 0; p5 < 8; p5++) s += sA[p4 * 128 + n2 * 8 + p5] * first[n3 * 8 + p5];
            tmp[k] = s;
        }
        __syncthreads();
        for (int k = t; k < 8192; k += 256) {
            int o = k >> 3, p3 = k & 7, n1 = o >> 7, rem = o & 127;
            float s = 0.f;
            #pragma unroll
            for (int p4 = 0; p4 < 8; p4++) s += sB[p3 * 64 + n1 * 8 + p4] * tmp[rem * 8 + p4];
            g_C1[k] = ALPHA_F * s;
        }
    }
}

// ---------------------------------------------------------------------------
// Kernel 2: Wt = W + A3*C1^T, fp16-pair split -> g_B2 = [Wh | Wl]
// ---------------------------------------------------------------------------
__global__ void combine_w(const float* __restrict__ W) {
    int o = blockIdx.x;
    __shared__ float cl[8];
    if (threadIdx.x < 8) cl[threadIdx.x] = g_C1[o * 8 + threadIdx.x];
    __syncthreads();
    float c0 = cl[0], c1 = cl[1], c2 = cl[2], c3 = cl[3];
    float c4 = cl[4], c5 = cl[5], c6 = cl[6], c7 = cl[7];
    for (int d = threadIdx.x; d < D_DIM; d += 256) {
        const float4* a = (const float4*)&g_A3[d * 8];
        float4 a0 = a[0], a1 = a[1];
        float s = W[(size_t)o * D_DIM + d];
        s += a0.x * c0 + a0.y * c1 + a0.z * c2 + a0.w * c3;
        s += a1.x * c4 + a1.y * c5 + a1.z * c6 + a1.w * c7;
        __half hb = __float2half_rn(s);
        __half lb = __float2half_rn(s - __half2float(hb));
        g_B2[(size_t)o * 2048 + d]        = hb;
        g_B2[(size_t)o * 2048 + 1024 + d] = lb;
    }
}

// ---------------------------------------------------------------------------
// Kernel 3: HMMA GEMM. CTA 128x128, BK=64 fp16, stage={A,Bh,Bl}=48KB,
// 2 stages (96KB), 2 CTA/SM, 16 chunks. Per chunk each A tile is multiplied
// by both Bh and Bl tiles (acc += xh*Wh + xh*Wl).
// 8 warps: warp (wm=w>>2, wn=w&3) owns 64(m) x 32(n).
// XOR swizzle: col16B ^= (row&7)<<4.
// Pipeline: issue(0); loop { wait0; sync; issue(c+1); compute(c) } — the
// next-iteration top barrier orders compute(c) reads before issue(c+2)'s
// rewrite of the same buffer.
// ---------------------------------------------------------------------------
#define NSTAGE 2
#define STAGE_BYTES 49152           // A 16K + Bh 16K + Bl 16K
#define SMEM_TOTAL (NSTAGE * STAGE_BYTES)
#define NCHUNK 16

extern __shared__ __align__(1024) char smem[];

__global__ __launch_bounds__(256, 2) void gemm_mma(const float* __restrict__ bias,
                                                   float* __restrict__ out) {
    const int tid = threadIdx.x;
    const int bn = blockIdx.x * 128;
    const int bm = blockIdx.y * 128;
    const uint32_t sbase = smem_u32(smem);

    const int w = tid >> 5, l = tid & 31;
    const int wm = w >> 2, wn = w & 3;

    // ---- cp.async lane mapping: 4 A-vectors + 4 B-row-vectors (each B row
    //      fetches Bh and Bl at +0 / +1024 elements) of 16B per thread ----
    uint32_t cp_dst[4];
    const __half* cp_srcA[4];
    const __half* cp_srcB[4];   // Bh source; Bl = +1024 elements
    #pragma unroll
    for (int i = 0; i < 4; i++) {
        int v = tid + 256 * i;            // 0..1023
        int row = v >> 3, seg = v & 7;    // 8 segs x 8 fp16 = 64 cols
        cp_dst[i]  = (uint32_t)(row * 128 + ((seg * 16) ^ ((row & 7) << 4)));
        cp_srcA[i] = g_A  + (size_t)(bm + row) * 1024 + seg * 8;
        cp_srcB[i] = g_B2 + (size_t)(bn + row) * 2048 + seg * 8;
    }

    // ---- ldmatrix lane address components ----
    const int arow = wm * 64 + (l & 15);
    const uint32_t axr = (uint32_t)((arow & 7) << 4);
    const uint32_t arb = (uint32_t)(arow * 128);
    const uint32_t ah16 = (uint32_t)((l >> 4) * 16);
    const int brow = wn * 32 + ((l >> 4) * 8) + (l & 7);
    const uint32_t bxr = (uint32_t)((l & 7) << 4);
    const uint32_t brb = (uint32_t)(brow * 128);
    const uint32_t bh16 = (uint32_t)(((l >> 3) & 1) * 16);

    float acc[4][4][4];
    #pragma unroll
    for (int i = 0; i < 4; i++)
        #pragma unroll
        for (int j = 0; j < 4; j++)
            #pragma unroll
            for (int k = 0; k < 4; k++) acc[i][j][k] = 0.f;

    auto issue_stage = [&](int t) {
        int kk = t * 64;                              // fp16 element offset
        uint32_t st = sbase + (t & 1) * STAGE_BYTES;
        #pragma unroll
        for (int i = 0; i < 4; i++) CP_ASYNC16(st + cp_dst[i],         cp_srcA[i] + kk);
        #pragma unroll
        for (int i = 0; i < 4; i++) CP_ASYNC16(st + 16384 + cp_dst[i], cp_srcB[i] + kk);
        #pragma unroll
        for (int i = 0; i < 4; i++) CP_ASYNC16(st + 32768 + cp_dst[i], cp_srcB[i] + 1024 + kk);
        CP_COMMIT();
    };

    issue_stage(0);

    for (int c = 0; c < NCHUNK; c++) {
        CP_WAIT0();
        __syncthreads();
        if (c + 1 < NCHUNK) issue_stage(c + 1);

        const uint32_t sA  = sbase + (c & 1) * STAGE_BYTES;
        const uint32_t sBh = sA + 16384;
        const uint32_t sBl = sA + 32768;
        #pragma unroll
        for (int ks = 0; ks < 4; ks++) {
            uint32_t a[4][4];
            uint32_t br[2][4];
            const uint32_t ac = (uint32_t)(ks * 32) + ah16;
            const uint32_t bc = (uint32_t)(ks * 32) + bh16;
            #pragma unroll
            for (int mf = 0; mf < 4; mf++)
                LDSM_X4(a[mf][0], a[mf][1], a[mf][2], a[mf][3],
                        sA + arb + mf * 2048 + (ac ^ axr));
            // --- high half of W ---
            #pragma unroll
            for (int nf2 = 0; nf2 < 2; nf2++)
                LDSM_X4(br[nf2][0], br[nf2][1], br[nf2][2], br[nf2][3],
                        sBh + brb + nf2 * 2048 + (bc ^ bxr));
            #pragma unroll
            for (int mf = 0; mf < 4; mf++)
                #pragma unroll
                for (int nf = 0; nf < 4; nf++)
                    MMA16816(acc[mf][nf], a[mf],
                             br[nf >> 1][(nf & 1) * 2], br[nf >> 1][(nf & 1) * 2 + 1]);
            // --- low half of W (same A registers) ---
            #pragma unroll
            for (int nf2 = 0; nf2 < 2; nf2++)
                LDSM_X4(br[nf2][0], br[nf2][1], br[nf2][2], br[nf2][3],
                        sBl + brb + nf2 * 2048 + (bc ^ bxr));
            #pragma unroll
            for (int mf = 0; mf < 4; mf++)
                #pragma unroll
                for (int nf = 0; nf < 4; nf++)
                    MMA16816(acc[mf][nf], a[mf],
                             br[nf >> 1][(nf & 1) * 2], br[nf >> 1][(nf & 1) * 2 + 1]);
        }
        // no trailing barrier: next iter's top barrier orders this iter's
        // reads before the (c+2) rewrite of this buffer
    }

    // ---- epilogue: bias + store ----
    float2 bv[4];
    #pragma unroll
    for (int nf = 0; nf < 4; nf++) {
        int col = bn + wn * 32 + nf * 8 + (l & 3) * 2;
        bv[nf] = *(const float2*)(bias + col);
    }
    #pragma unroll
    for (int mf = 0; mf < 4; mf++) {
        int r0 = bm + wm * 64 + mf * 16 + (l >> 2);
        #pragma unroll
        for (int nf = 0; nf < 4; nf++) {
            int col = bn + wn * 32 + nf * 8 + (l & 3) * 2;
            float2 v0 = {acc[mf][nf][0] + bv[nf].x, acc[mf][nf][1] + bv[nf].y};
            float2 v1 = {acc[mf][nf][2] + bv[nf].x, acc[mf][nf][3] + bv[nf].y};
            *(float2*)(out + (size_t)r0 * D_DIM + col) = v0;
            *(float2*)(out + (size_t)(r0 + 8) * D_DIM + col) = v1;
        }
    }
}

// ---------------------------------------------------------------------------
extern "C" void kernel_launch(void* const* d_in, const int* in_sizes, int n_in,
                              void* d_out, int out_size) {
    const float* x  = (const float*)d_in[0];
    const float* W  = (const float*)d_in[1];
    const float* b  = (const float*)d_in[2];
    const float* c0 = (const float*)d_in[3];
    const float* c1 = (const float*)d_in[4];
    const float* c2 = (const float*)d_in[5];
    const float* c3 = (const float*)d_in[6];
    const float* c4 = (const float*)d_in[7];
    const float* c5 = (const float*)d_in[8];
    float* out = (float*)d_out;

    cudaFuncSetAttribute(gemm_mma, cudaFuncAttributeMaxDynamicSharedMemorySize, SMEM_TOTAL);

    convert_x<<<(M_ROWS * D_DIM / 8) / 256, 256>>>(x, c0, c1, c2, c3, c4, c5);
    combine_w<<<D_DIM, 256>>>(W);
    dim3 grid(D_DIM / 128, M_ROWS / 128);
    gemm_mma<<<grid, 256, SMEM_TOTAL>>>(b, out);
}